// round 3
// baseline (speedup 1.0000x reference)
#include <cuda_runtime.h>
#include <cstdint>
#include <math.h>

// Problem dims
#define B_   512
#define T_   512
#define IN_  128
#define H_   256
#define G3_  768   // 3*H
#define OUT_ 128

// Scratch (device globals — allocation inside kernel_launch is forbidden).
// ig layout: [B][T][3H] fp32 (row index = b*T + t, matching x's (B,T,IN) flattening)
__device__ float g_ig[(size_t)B_ * T_ * G3_];     // ~805 MB
__device__ float g_hfin[(size_t)B_ * H_];

// ---------------------------------------------------------------------------
// Phase 1: ig[b,t,:] = x[b,t,:] @ W_ih^T + bias_g
// C[M=262144][768] = X[M][128] @ W^T, classic 64x64 tile, K staged in 2 chunks.
// ---------------------------------------------------------------------------
__global__ void __launch_bounds__(256) k_ih(const float* __restrict__ X,
                                            const float* __restrict__ W,
                                            const float* __restrict__ bias)
{
    __shared__ float sX[64 * 68];   // [m][k], padded stride 68
    __shared__ float sW[64 * 64];   // [k][n] (transposed in staging)

    const int tid = threadIdx.x;
    const int bm = blockIdx.x, bn = blockIdx.y;
    const int tm = tid >> 4, tn = tid & 15;

    float acc[4][4];
#pragma unroll
    for (int i = 0; i < 4; i++)
#pragma unroll
        for (int j = 0; j < 4; j++) acc[i][j] = 0.f;

    for (int kk = 0; kk < 128; kk += 64) {
        // stage X tile (64 rows x 64 k)
        {
            const int m  = tid >> 2;
            const int kq = (tid & 3) << 4;
            const float4* src = (const float4*)(X + ((size_t)(bm * 64 + m)) * 128 + kk + kq);
            float4* dst = (float4*)(sX + m * 68 + kq);
            dst[0] = src[0]; dst[1] = src[1]; dst[2] = src[2]; dst[3] = src[3];
        }
        // stage W tile transposed: sW[k][n]
        {
            const int n  = tid & 63;
            const int kq = (tid >> 6) << 4;
            const float4* src = (const float4*)(W + ((size_t)(bn * 64 + n)) * 128 + kk + kq);
#pragma unroll
            for (int q = 0; q < 4; q++) {
                float4 v = src[q];
                float* d = sW + (kq + q * 4) * 64 + n;
                d[0] = v.x; d[64] = v.y; d[128] = v.z; d[192] = v.w;
            }
        }
        __syncthreads();

#pragma unroll 8
        for (int k = 0; k < 64; k++) {
            const float a0 = sX[(tm * 4 + 0) * 68 + k];
            const float a1 = sX[(tm * 4 + 1) * 68 + k];
            const float a2 = sX[(tm * 4 + 2) * 68 + k];
            const float a3 = sX[(tm * 4 + 3) * 68 + k];
            const float4 b = *(const float4*)(sW + k * 64 + tn * 4);
            acc[0][0] += a0 * b.x; acc[0][1] += a0 * b.y; acc[0][2] += a0 * b.z; acc[0][3] += a0 * b.w;
            acc[1][0] += a1 * b.x; acc[1][1] += a1 * b.y; acc[1][2] += a1 * b.z; acc[1][3] += a1 * b.w;
            acc[2][0] += a2 * b.x; acc[2][1] += a2 * b.y; acc[2][2] += a2 * b.z; acc[2][3] += a2 * b.w;
            acc[3][0] += a3 * b.x; acc[3][1] += a3 * b.y; acc[3][2] += a3 * b.z; acc[3][3] += a3 * b.w;
        }
        __syncthreads();
    }

    const float4 bb = *(const float4*)(bias + bn * 64 + tn * 4);
#pragma unroll
    for (int i = 0; i < 4; i++) {
        float4 o;
        o.x = acc[i][0] + bb.x;
        o.y = acc[i][1] + bb.y;
        o.z = acc[i][2] + bb.z;
        o.w = acc[i][3] + bb.w;
        *(float4*)(g_ig + ((size_t)(bm * 64 + tm * 4 + i)) * G3_ + bn * 64 + tn * 4) = o;
    }
}

// ---------------------------------------------------------------------------
// Phase 2: GRU recurrence. Cluster of 4 CTAs; rank c owns hidden units
// [c*64, c*64+64) and keeps W_hh rows {u, 256+u, 512+u} resident in smem.
// Cluster handles 16 batch rows; h exchanged per step via DSMEM.
// ---------------------------------------------------------------------------
__device__ __forceinline__ uint32_t smem_u32(const void* p) {
    uint32_t a;
    asm("{ .reg .u64 t; cvta.to.shared.u64 t, %1; cvt.u32.u64 %0, t; }" : "=r"(a) : "l"(p));
    return a;
}
__device__ __forceinline__ uint32_t mapa_u32(uint32_t a, uint32_t rank) {
    uint32_t r;
    asm("mapa.shared::cluster.u32 %0, %1, %2;" : "=r"(r) : "r"(a), "r"(rank));
    return r;
}
__device__ __forceinline__ void stc_f32(uint32_t a, float v) {
    asm volatile("st.shared::cluster.f32 [%0], %1;" :: "r"(a), "f"(v) : "memory");
}
__device__ __forceinline__ void cluster_sync_() {
    asm volatile("barrier.cluster.arrive.aligned;" ::: "memory");
    asm volatile("barrier.cluster.wait.aligned;"   ::: "memory");
}
__device__ __forceinline__ float gru_cell(float igr, float igz, float ign,
                                          float ar, float az, float an,
                                          float bnv, float hp) {
    float r = 1.f / (1.f + expf(-(igr + ar)));
    float z = 1.f / (1.f + expf(-(igz + az)));
    float n = tanhf(ign + r * (an + bnv));
    return n + z * (hp - n);
}

// dynamic smem: sW 3*256*64 + sH0 16*256 + sH1 16*256 = 57344 floats = 229376 B
#define REC_SMEM_BYTES (57344 * 4)

__global__ void __launch_bounds__(256, 1) __cluster_dims__(4, 1, 1)
k_rec(const float* __restrict__ Whh, const float* __restrict__ bn)
{
    extern __shared__ float sm[];
    float* sW  = sm;            // [gate][k][unit] : 3*256*64
    float* sH0 = sm + 49152;    // [row][k] : 16*256
    float* sH1 = sm + 53248;

    const int tid = threadIdx.x;
    const int c   = blockIdx.x & 3;   // cluster rank
    const int cl  = blockIdx.x >> 2;  // cluster id (0..31), owns batch rows [cl*16, cl*16+16)

    // Stage W_hh chunk, transposed to unit-contiguous layout (conflict-free LDS.64 later)
    for (int flat = tid; flat < 3 * 64 * 64; flat += 256) {
        const int kv  = flat / 192;
        const int rem = flat - kv * 192;
        const int g   = rem >> 6;
        const int uu  = rem & 63;
        const float4 v = *(const float4*)(Whh + ((size_t)(g * 256 + c * 64 + uu)) * 256 + kv * 4);
        float* d = sW + (g * 256 + kv * 4) * 64 + uu;
        d[0] = v.x; d[64] = v.y; d[128] = v.z; d[192] = v.w;
    }
    for (int i = tid; i < 4096; i += 256) sH0[i] = 0.f;  // h_0 = 0
    __syncthreads();
    cluster_sync_();  // all peers' smem initialized before any remote store

    const int g2 = tid & 31;        // unit-pair index (units 2*g2, 2*g2+1)
    const int rg = tid >> 5;        // row group (2 rows each)
    const int u0 = g2 * 2;
    const int gu = c * 64 + u0;     // global hidden-unit index
    const int r0 = rg * 2;          // local row
    const int b0 = cl * 16 + r0;    // global batch row

    const float bn0 = bn[gu], bn1 = bn[gu + 1];

    // DSMEM peer base addresses (address math valid before use; data ordered by cluster barrier)
    const uint32_t a0 = smem_u32(sH0), a1 = smem_u32(sH1);
    uint32_t p0[4], p1[4];
#pragma unroll
    for (int r = 0; r < 4; r++) { p0[r] = mapa_u32(a0, r); p1[r] = mapa_u32(a1, r); }

    const float2* wr = (const float2*)(sW);
    const float2* wz = (const float2*)(sW + 256 * 64);
    const float2* wn = (const float2*)(sW + 512 * 64);

    const float* igb0 = g_ig + (size_t)b0 * T_ * G3_ + gu;
    const float* igb1 = igb0 + (size_t)T_ * G3_;

    for (int t = 0; t < T_; t++) {
        const float* sHc      = (t & 1) ? sH1 : sH0;
        const uint32_t* pnext = (t & 1) ? p0 : p1;

        // prefetch input gates for this step (consumed ~12K cycles later)
        const size_t tb = (size_t)t * G3_;
        const float2 igr0 = *(const float2*)(igb0 + tb);
        const float2 igz0 = *(const float2*)(igb0 + tb + 256);
        const float2 ign0 = *(const float2*)(igb0 + tb + 512);
        const float2 igr1 = *(const float2*)(igb1 + tb);
        const float2 igz1 = *(const float2*)(igb1 + tb + 256);
        const float2 ign1 = *(const float2*)(igb1 + tb + 512);

        float aR[2][2] = {{0.f, 0.f}, {0.f, 0.f}};
        float aZ[2][2] = {{0.f, 0.f}, {0.f, 0.f}};
        float aN[2][2] = {{0.f, 0.f}, {0.f, 0.f}};

        const float* hA = sHc + r0 * 256;
        const float* hB = hA + 256;

#pragma unroll 8
        for (int k = 0; k < 256; k++) {
            const float2 w0 = wr[k * 32 + g2];
            const float2 w1 = wz[k * 32 + g2];
            const float2 w2 = wn[k * 32 + g2];
            const float h0v = hA[k];   // warp-broadcast
            const float h1v = hB[k];
            aR[0][0] += w0.x * h0v; aR[0][1] += w0.x * h1v;
            aR[1][0] += w0.y * h0v; aR[1][1] += w0.y * h1v;
            aZ[0][0] += w1.x * h0v; aZ[0][1] += w1.x * h1v;
            aZ[1][0] += w1.y * h0v; aZ[1][1] += w1.y * h1v;
            aN[0][0] += w2.x * h0v; aN[0][1] += w2.x * h1v;
            aN[1][0] += w2.y * h0v; aN[1][1] += w2.y * h1v;
        }

        // previous h for own units
        const float hp00 = sHc[r0 * 256 + gu];
        const float hp01 = sHc[(r0 + 1) * 256 + gu];
        const float hp10 = sHc[r0 * 256 + gu + 1];
        const float hp11 = sHc[(r0 + 1) * 256 + gu + 1];

        const float h00 = gru_cell(igr0.x, igz0.x, ign0.x, aR[0][0], aZ[0][0], aN[0][0], bn0, hp00);
        const float h01 = gru_cell(igr1.x, igz1.x, ign1.x, aR[0][1], aZ[0][1], aN[0][1], bn0, hp01);
        const float h10 = gru_cell(igr0.y, igz0.y, ign0.y, aR[1][0], aZ[1][0], aN[1][0], bn1, hp10);
        const float h11 = gru_cell(igr1.y, igz1.y, ign1.y, aR[1][1], aZ[1][1], aN[1][1], bn1, hp11);

        const uint32_t o00 = (uint32_t)((r0 * 256 + gu) * 4);
        const uint32_t o01 = (uint32_t)(((r0 + 1) * 256 + gu) * 4);
#pragma unroll
        for (int r = 0; r < 4; r++) {
            const uint32_t base = pnext[r];
            stc_f32(base + o00,     h00);
            stc_f32(base + o00 + 4, h10);
            stc_f32(base + o01,     h01);
            stc_f32(base + o01 + 4, h11);
        }
        cluster_sync_();  // release stores / acquire for next step's reads
    }

    // T_ even -> final h lives in sH0 (writes at t=511 targeted sH0)
    for (int i = tid; i < 16 * 64; i += 256) {
        const int row = i >> 6, uu = i & 63;
        g_hfin[(size_t)(cl * 16 + row) * H_ + c * 64 + uu] = sH0[row * 256 + c * 64 + uu];
    }
}

// ---------------------------------------------------------------------------
// Phase 3: out = h_final @ w_lin^T + bias_out   (512 x 128, trivial)
// ---------------------------------------------------------------------------
__global__ void __launch_bounds__(128) k_out(const float* __restrict__ wl,
                                             const float* __restrict__ bo,
                                             float* __restrict__ out)
{
    __shared__ float sh[256];
    const int b = blockIdx.x, o = threadIdx.x;
    sh[o]       = g_hfin[(size_t)b * H_ + o];
    sh[o + 128] = g_hfin[(size_t)b * H_ + o + 128];
    __syncthreads();

    float acc = bo[o];
    const float4* wp = (const float4*)(wl + (size_t)o * H_);
#pragma unroll 8
    for (int q = 0; q < 64; q++) {
        const float4 w = wp[q];
        const float4 h = *(const float4*)(sh + q * 4);
        acc += w.x * h.x + w.y * h.y + w.z * h.z + w.w * h.w;
    }
    out[(size_t)b * OUT_ + o] = acc;
}

// ---------------------------------------------------------------------------
extern "C" void kernel_launch(void* const* d_in, const int* in_sizes, int n_in,
                              void* d_out, int out_size)
{
    (void)in_sizes; (void)n_in; (void)out_size;
    const float* x   = (const float*)d_in[0];  // (B,T,IN)
    const float* wih = (const float*)d_in[1];  // (3H,IN)
    const float* whh = (const float*)d_in[2];  // (3H,H)
    const float* bg  = (const float*)d_in[3];  // (3H)
    const float* bnn = (const float*)d_in[4];  // (H)
    const float* wl  = (const float*)d_in[5];  // (OUT,H)
    const float* bo  = (const float*)d_in[6];  // (OUT)
    float* out = (float*)d_out;                // (B,OUT)

    cudaFuncSetAttribute(k_rec, cudaFuncAttributeMaxDynamicSharedMemorySize, REC_SMEM_BYTES);

    k_ih<<<dim3((B_ * T_) / 64, G3_ / 64), 256>>>(x, wih, bg);
    k_rec<<<128, 256, REC_SMEM_BYTES>>>(whh, bnn);
    k_out<<<B_, 128>>>(wl, bo, out);
}

// round 4
// speedup vs baseline: 1.3141x; 1.3141x over previous
#include <cuda_runtime.h>
#include <cstdint>
#include <math.h>

// Problem dims
#define B_   512
#define T_   512
#define IN_  128
#define H_   256
#define G3_  768   // 3*H
#define OUT_ 128

// Scratch (device globals — allocation inside kernel_launch is forbidden).
__device__ float g_ig[(size_t)B_ * T_ * G3_];     // ~805 MB  [B][T][3H]
__device__ float g_hfin[(size_t)B_ * H_];

// ---------------- packed fp32 helpers (Blackwell f32x2) --------------------
__device__ __forceinline__ unsigned long long pk2(float lo, float hi) {
    unsigned long long r;
    asm("mov.b64 %0, {%1, %2};" : "=l"(r) : "f"(lo), "f"(hi));
    return r;
}
__device__ __forceinline__ void fma2(unsigned long long& d,
                                     unsigned long long a, unsigned long long b) {
    asm("fma.rn.f32x2 %0, %1, %2, %0;" : "+l"(d) : "l"(a), "l"(b));
}
__device__ __forceinline__ float2 upk(unsigned long long v) {
    float2 f;
    asm("mov.b64 {%0, %1}, %2;" : "=f"(f.x), "=f"(f.y) : "l"(v));
    return f;
}

// ---------------------------------------------------------------------------
// Phase 1: ig[b,t,:] = x[b,t,:] @ W_ih^T + bias_g   (M=262144, N=768, K=128)
// 64x64 tile, packed f32x2 accumulation (8 FFMA2 per thread per k).
// ---------------------------------------------------------------------------
__global__ void __launch_bounds__(256) k_ih(const float* __restrict__ X,
                                            const float* __restrict__ W,
                                            const float* __restrict__ bias)
{
    __shared__ float sX[64 * 68];   // [m][k], padded stride 68
    __shared__ float sW[64 * 64];   // [k][n] (transposed in staging)

    const int tid = threadIdx.x;
    const int bm = blockIdx.x, bn = blockIdx.y;
    const int tm = tid >> 4, tn = tid & 15;

    unsigned long long acc[4][2];
#pragma unroll
    for (int i = 0; i < 4; i++) { acc[i][0] = 0ULL; acc[i][1] = 0ULL; }

    for (int kk = 0; kk < 128; kk += 64) {
        // stage X tile (64 rows x 64 k)
        {
            const int m  = tid >> 2;
            const int kq = (tid & 3) << 4;
            const float4* src = (const float4*)(X + ((size_t)(bm * 64 + m)) * 128 + kk + kq);
            float4* dst = (float4*)(sX + m * 68 + kq);
            dst[0] = src[0]; dst[1] = src[1]; dst[2] = src[2]; dst[3] = src[3];
        }
        // stage W tile transposed: sW[k][n]
        {
            const int n  = tid & 63;
            const int kq = (tid >> 6) << 4;
            const float4* src = (const float4*)(W + ((size_t)(bn * 64 + n)) * 128 + kk + kq);
#pragma unroll
            for (int q = 0; q < 4; q++) {
                float4 v = src[q];
                float* d = sW + (kq + q * 4) * 64 + n;
                d[0] = v.x; d[64] = v.y; d[128] = v.z; d[192] = v.w;
            }
        }
        __syncthreads();

#pragma unroll 8
        for (int k = 0; k < 64; k++) {
            const float a0 = sX[(tm * 4 + 0) * 68 + k];
            const float a1 = sX[(tm * 4 + 1) * 68 + k];
            const float a2 = sX[(tm * 4 + 2) * 68 + k];
            const float a3 = sX[(tm * 4 + 3) * 68 + k];
            const unsigned long long b01 = *(const unsigned long long*)(sW + k * 64 + tn * 4);
            const unsigned long long b23 = *(const unsigned long long*)(sW + k * 64 + tn * 4 + 2);
            const unsigned long long p0 = pk2(a0, a0);
            const unsigned long long p1 = pk2(a1, a1);
            const unsigned long long p2 = pk2(a2, a2);
            const unsigned long long p3 = pk2(a3, a3);
            fma2(acc[0][0], p0, b01); fma2(acc[0][1], p0, b23);
            fma2(acc[1][0], p1, b01); fma2(acc[1][1], p1, b23);
            fma2(acc[2][0], p2, b01); fma2(acc[2][1], p2, b23);
            fma2(acc[3][0], p3, b01); fma2(acc[3][1], p3, b23);
        }
        __syncthreads();
    }

    const float4 bb = *(const float4*)(bias + bn * 64 + tn * 4);
#pragma unroll
    for (int i = 0; i < 4; i++) {
        const float2 lo = upk(acc[i][0]);
        const float2 hi = upk(acc[i][1]);
        float4 o;
        o.x = lo.x + bb.x; o.y = lo.y + bb.y;
        o.z = hi.x + bb.z; o.w = hi.y + bb.w;
        *(float4*)(g_ig + ((size_t)(bm * 64 + tm * 4 + i)) * G3_ + bn * 64 + tn * 4) = o;
    }
}

// ---------------------------------------------------------------------------
// Phase 2: GRU recurrence. Cluster of 4 CTAs; rank c owns 64 hidden units and
// keeps its W_hh chunk in smem (192 KB). Cluster handles 16 batch rows.
// h stored transposed as float2[rowpair][k] so row-pairs load packed; the
// hidden GEMM accumulates with packed f32x2 FMAs (6 FFMA2 / thread / k).
// Thread layout: 256 thr = 64 units x 4 rowgroups (4 rows each).
// ---------------------------------------------------------------------------
__device__ __forceinline__ uint32_t smem_u32(const void* p) {
    uint32_t a;
    asm("{ .reg .u64 t; cvta.to.shared.u64 t, %1; cvt.u32.u64 %0, t; }" : "=r"(a) : "l"(p));
    return a;
}
__device__ __forceinline__ uint32_t mapa_u32(uint32_t a, uint32_t rank) {
    uint32_t r;
    asm("mapa.shared::cluster.u32 %0, %1, %2;" : "=r"(r) : "r"(a), "r"(rank));
    return r;
}
__device__ __forceinline__ void stc_b64(uint32_t a, unsigned long long v) {
    asm volatile("st.shared::cluster.b64 [%0], %1;" :: "r"(a), "l"(v) : "memory");
}
__device__ __forceinline__ void cluster_sync_() {
    asm volatile("barrier.cluster.arrive.aligned;" ::: "memory");
    asm volatile("barrier.cluster.wait.aligned;"   ::: "memory");
}
__device__ __forceinline__ float gru_cell(float igr, float igz, float ign,
                                          float ar, float az, float an,
                                          float bnv, float hp) {
    float r = __fdividef(1.f, 1.f + __expf(-(igr + ar)));
    float z = __fdividef(1.f, 1.f + __expf(-(igz + az)));
    float n = tanhf(ign + r * (an + bnv));
    return n + z * (hp - n);
}

// smem: sW 3*256*64 floats (192KB) + 2 x h buffer (8 rowpairs * 256 k float2 = 16KB)
#define REC_SMEM_BYTES ((3 * 256 * 64 + 2 * 8 * 256 * 2) * 4)   // 229376 B

__global__ void __launch_bounds__(256, 1) __cluster_dims__(4, 1, 1)
k_rec(const float* __restrict__ Whh, const float* __restrict__ bn)
{
    extern __shared__ float sm[];
    float*  sW  = sm;                         // [gate][k][unit] : 3*256*64
    float2* sH0 = (float2*)(sm + 49152);      // [rowpair(8)][k(256)]
    float2* sH1 = (float2*)(sm + 53248);

    const int tid = threadIdx.x;
    const int c   = blockIdx.x & 3;   // cluster rank (unit chunk)
    const int cl  = blockIdx.x >> 2;  // cluster id: batch rows [cl*16, cl*16+16)

    // Stage W_hh chunk, transposed to unit-contiguous layout
    for (int flat = tid; flat < 3 * 64 * 64; flat += 256) {
        const int kv  = flat / 192;
        const int rem = flat - kv * 192;
        const int g   = rem >> 6;
        const int uu  = rem & 63;
        const float4 v = *(const float4*)(Whh + ((size_t)(g * 256 + c * 64 + uu)) * 256 + kv * 4);
        float* d = sW + (g * 256 + kv * 4) * 64 + uu;
        d[0] = v.x; d[64] = v.y; d[128] = v.z; d[192] = v.w;
    }
    for (int i = tid; i < 2048; i += 256) sH0[i] = make_float2(0.f, 0.f);  // h_0 = 0
    __syncthreads();
    cluster_sync_();  // peers' smem initialized before any remote store

    const int u   = tid & 63;         // unit within chunk
    const int rg  = tid >> 6;         // rowgroup 0..3 (4 rows each)
    const int gu  = c * 64 + u;       // global hidden-unit index
    const int rp0 = rg * 2;           // rowpairs rp0, rp0+1
    const int b0  = cl * 16 + rg * 4; // first global batch row of this thread

    const float bnv = bn[gu];

    const uint32_t a0 = smem_u32(sH0), a1 = smem_u32(sH1);
    uint32_t p0[4], p1[4];
#pragma unroll
    for (int r = 0; r < 4; r++) { p0[r] = mapa_u32(a0, r); p1[r] = mapa_u32(a1, r); }

    const float* wr = sW + u;
    const float* wz = sW + 256 * 64 + u;
    const float* wn = sW + 512 * 64 + u;

    const size_t rstr = (size_t)T_ * G3_;   // batch-row stride in g_ig
    const float* igb = g_ig + (size_t)b0 * rstr + gu;

    const uint32_t o0 = (uint32_t)((rp0 * 256 + gu) * 8);
    const uint32_t o1 = (uint32_t)(((rp0 + 1) * 256 + gu) * 8);

    for (int t = 0; t < T_; t++) {
        const float2*   sHc   = (t & 1) ? sH1 : sH0;
        const uint32_t* pnext = (t & 1) ? p0 : p1;

        // prefetch input gates for this step (consumed ~7K cycles later)
        const size_t tb = (size_t)t * G3_;
        float igr[4], igz[4], ign[4];
#pragma unroll
        for (int j = 0; j < 4; j++) {
            const float* p = igb + (size_t)j * rstr + tb;
            igr[j] = p[0]; igz[j] = p[256]; ign[j] = p[512];
        }

        unsigned long long aR0 = 0ULL, aR1 = 0ULL;
        unsigned long long aZ0 = 0ULL, aZ1 = 0ULL;
        unsigned long long aN0 = 0ULL, aN1 = 0ULL;

        const unsigned long long* h0p = (const unsigned long long*)(sHc + rp0 * 256);
        const unsigned long long* h1p = (const unsigned long long*)(sHc + (rp0 + 1) * 256);

#pragma unroll 8
        for (int k = 0; k < 256; k++) {
            const float w0 = wr[k * 64];
            const float w1 = wz[k * 64];
            const float w2 = wn[k * 64];
            const unsigned long long h0 = h0p[k];   // broadcast: rows (rg*4, rg*4+1)
            const unsigned long long h1 = h1p[k];   // broadcast: rows (rg*4+2, rg*4+3)
            const unsigned long long w02 = pk2(w0, w0);
            const unsigned long long w12 = pk2(w1, w1);
            const unsigned long long w22 = pk2(w2, w2);
            fma2(aR0, w02, h0); fma2(aR1, w02, h1);
            fma2(aZ0, w12, h0); fma2(aZ1, w12, h1);
            fma2(aN0, w22, h0); fma2(aN1, w22, h1);
        }

        // previous h for own unit, 4 rows
        const float2 hp01 = sHc[rp0 * 256 + gu];
        const float2 hp23 = sHc[(rp0 + 1) * 256 + gu];

        const float2 ar01 = upk(aR0), ar23 = upk(aR1);
        const float2 az01 = upk(aZ0), az23 = upk(aZ1);
        const float2 an01 = upk(aN0), an23 = upk(aN1);

        const float h0n = gru_cell(igr[0], igz[0], ign[0], ar01.x, az01.x, an01.x, bnv, hp01.x);
        const float h1n = gru_cell(igr[1], igz[1], ign[1], ar01.y, az01.y, an01.y, bnv, hp01.y);
        const float h2n = gru_cell(igr[2], igz[2], ign[2], ar23.x, az23.x, an23.x, bnv, hp23.x);
        const float h3n = gru_cell(igr[3], igz[3], ign[3], ar23.y, az23.y, an23.y, bnv, hp23.y);

        const unsigned long long hn01 = pk2(h0n, h1n);
        const unsigned long long hn23 = pk2(h2n, h3n);

#pragma unroll
        for (int r = 0; r < 4; r++) {
            stc_b64(pnext[r] + o0, hn01);
            stc_b64(pnext[r] + o1, hn23);
        }
        cluster_sync_();  // release stores / acquire for next step's reads
    }

    // T_ even -> final h lives in sH0
    for (int i = tid; i < 8 * 64; i += 256) {
        const int rp = i >> 6, uu = i & 63;
        const float2 v = sH0[rp * 256 + c * 64 + uu];
        float* d = g_hfin + (size_t)(cl * 16 + rp * 2) * H_ + c * 64 + uu;
        d[0]  = v.x;
        d[H_] = v.y;
    }
}

// ---------------------------------------------------------------------------
// Phase 3: out = h_final @ w_lin^T + bias_out   (512 x 128, trivial)
// ---------------------------------------------------------------------------
__global__ void __launch_bounds__(128) k_out(const float* __restrict__ wl,
                                             const float* __restrict__ bo,
                                             float* __restrict__ out)
{
    __shared__ float sh[256];
    const int b = blockIdx.x, o = threadIdx.x;
    sh[o]       = g_hfin[(size_t)b * H_ + o];
    sh[o + 128] = g_hfin[(size_t)b * H_ + o + 128];
    __syncthreads();

    float acc = bo[o];
    const float4* wp = (const float4*)(wl + (size_t)o * H_);
#pragma unroll 8
    for (int q = 0; q < 64; q++) {
        const float4 w = wp[q];
        const float4 h = *(const float4*)(sh + q * 4);
        acc += w.x * h.x + w.y * h.y + w.z * h.z + w.w * h.w;
    }
    out[(size_t)b * OUT_ + o] = acc;
}

// ---------------------------------------------------------------------------
extern "C" void kernel_launch(void* const* d_in, const int* in_sizes, int n_in,
                              void* d_out, int out_size)
{
    (void)in_sizes; (void)n_in; (void)out_size;
    const float* x   = (const float*)d_in[0];  // (B,T,IN)
    const float* wih = (const float*)d_in[1];  // (3H,IN)
    const float* whh = (const float*)d_in[2];  // (3H,H)
    const float* bg  = (const float*)d_in[3];  // (3H)
    const float* bnn = (const float*)d_in[4];  // (H)
    const float* wl  = (const float*)d_in[5];  // (OUT,H)
    const float* bo  = (const float*)d_in[6];  // (OUT)
    float* out = (float*)d_out;                // (B,OUT)

    cudaFuncSetAttribute(k_rec, cudaFuncAttributeMaxDynamicSharedMemorySize, REC_SMEM_BYTES);

    k_ih<<<dim3((B_ * T_) / 64, G3_ / 64), 256>>>(x, wih, bg);
    k_rec<<<128, 256, REC_SMEM_BYTES>>>(whh, bnn);
    k_out<<<B_, 128>>>(wl, bo, out);
}